// round 9
// baseline (speedup 1.0000x reference)
#include <cuda_runtime.h>
#include <cstdint>

#define B_ 256
#define T_ 512
#define D_ 128
#define H_ 128
#define G_ 384          // 3H, gate order z|r|h
#define BT_ (B_*T_)

__device__ float g_xp[(size_t)BT_ * G_];   // 201 MB scratch
__device__ float g_h0[(size_t)BT_ * H_];   // 67 MB scratch

typedef unsigned long long u64;

static __device__ __forceinline__ u64 pack2(float a, float b) {
    u64 r; asm("mov.b64 %0, {%1, %2};" : "=l"(r) : "f"(a), "f"(b)); return r;
}
static __device__ __forceinline__ void unpack2(u64 v, float &a, float &b) {
    asm("mov.b64 {%0, %1}, %2;" : "=f"(a), "=f"(b) : "l"(v));
}
static __device__ __forceinline__ u64 fma2(u64 a, u64 b, u64 c) {
    u64 d; asm("fma.rn.f32x2 %0, %1, %2, %3;" : "=l"(d) : "l"(a), "l"(b), "l"(c)); return d;
}
static __device__ __forceinline__ float sigf(float a) {
    return __fdividef(1.0f, 1.0f + __expf(-a));
}
static __device__ __forceinline__ float tanh_fast(float a) {
    return __fdividef(2.0f, 1.0f + __expf(-2.0f * a)) - 1.0f;
}

// ---------------------------------------------------------------------------
// Projection (R6 f32x2 version, measured 332us/layer): 384 threads =
// 4 kg x 96 jg x 4 cols; W in regs; 8 rows/iter; smem partial reduction.
// ---------------------------------------------------------------------------
#define PR_ 8
__global__ __launch_bounds__(384, 1)
void proj_kernel(const float* __restrict__ x, const float* __restrict__ W,
                 const float* __restrict__ bias, float* __restrict__ out,
                 int rows_per_block)
{
    __shared__ __align__(16) float x_sm[2][PR_][D_];
    __shared__ __align__(16) float part[PR_][4][G_];   // 48 KB
    const int tid = threadIdx.x;
    const int kg  = tid / 96;
    const int jg  = tid - kg * 96;
    const int j0  = jg * 4;
    const int kb  = kg * 32;

    u64 w2[16][4];
#pragma unroll
    for (int i = 0; i < 16; i++)
#pragma unroll
        for (int jj = 0; jj < 4; jj++)
            w2[i][jj] = pack2(W[(kb + 2*i) * G_ + j0 + jj],
                              W[(kb + 2*i + 1) * G_ + j0 + jj]);
    const float bj = bias[tid];

    const int row0 = blockIdx.x * rows_per_block;
    if (tid < PR_ * D_ / 4)
        ((float4*)&x_sm[0][0][0])[tid] =
            ((const float4*)(x + (size_t)row0 * D_))[tid];
    __syncthreads();

    const int iters = rows_per_block / PR_;
    int buf = 0;
    for (int it = 0; it < iters; it++) {
        const int rbase = row0 + it * PR_;
        float4 nx;
        const bool pre = (it + 1 < iters) && (tid < PR_ * D_ / 4);
        if (pre)
            nx = ((const float4*)(x + (size_t)(rbase + PR_) * D_))[tid];

#pragma unroll
        for (int r = 0; r < PR_; r++) {
            u64 acc0 = 0, acc1 = 0, acc2 = 0, acc3 = 0;
            const float* xs = &x_sm[buf][r][kb];
#pragma unroll
            for (int i2 = 0; i2 < 8; i2++) {
                ulonglong2 hv = *(const ulonglong2*)&xs[4*i2];
                acc0 = fma2(hv.x, w2[2*i2][0],     acc0);
                acc0 = fma2(hv.y, w2[2*i2 + 1][0], acc0);
                acc1 = fma2(hv.x, w2[2*i2][1],     acc1);
                acc1 = fma2(hv.y, w2[2*i2 + 1][1], acc1);
                acc2 = fma2(hv.x, w2[2*i2][2],     acc2);
                acc2 = fma2(hv.y, w2[2*i2 + 1][2], acc2);
                acc3 = fma2(hv.x, w2[2*i2][3],     acc3);
                acc3 = fma2(hv.y, w2[2*i2 + 1][3], acc3);
            }
            float4 p; float a, b;
            unpack2(acc0, a, b); p.x = a + b;
            unpack2(acc1, a, b); p.y = a + b;
            unpack2(acc2, a, b); p.z = a + b;
            unpack2(acc3, a, b); p.w = a + b;
            *(float4*)&part[r][kg][j0] = p;
        }
        if (pre)
            ((float4*)&x_sm[buf ^ 1][0][0])[tid] = nx;
        __syncthreads();
#pragma unroll
        for (int r = 0; r < PR_; r++) {
            float s = part[r][0][tid] + part[r][1][tid]
                    + part[r][2][tid] + part[r][3][tid] + bj;
            out[(size_t)(rbase + r) * G_ + tid] = s;
        }
        __syncthreads();
        buf ^= 1;
    }
}

// ---------------------------------------------------------------------------
// GRU scan, warp-specialized skew. 288 threads:
//   tid < 256 : matvec warps. One row per phase (row = p&1, t = p>>1).
//     Layout as R6: kg = lane>>4 (k-half), u = warp*16 + lane&15,
//     weights U[64k x {u,u+128,u+256}] in regs. shfl.xor(16) k-reduce,
//     kg==0 lanes store raw rec sums to rec_sm[row].
//   warp 8 (32 thr): epilogue for the OTHER row (phase p-1's rec): 4 units
//     per thread, gates + h/out stores; xp prefetched one phase ahead.
// One barrier per phase; h_sm/rec_sm rows are disjoint between roles.
// ---------------------------------------------------------------------------
__global__ __launch_bounds__(288, 1)
void gru_scan(const float* __restrict__ U, const float* __restrict__ brec,
              const float* __restrict__ xp, float* __restrict__ out)
{
    __shared__ __align__(16) float h_sm[2][2][68];   // [row][kg][64 used]
    __shared__ __align__(16) float rec_sm[2][G_];    // raw sums (no bias)
    const int tid = threadIdx.x;
    const int b0  = blockIdx.x * 2;

    if (tid < 256) {
        // ---------------- matvec role ----------------
        const int lane = tid & 31;
        const int kg   = lane >> 4;
        const int u    = (tid >> 5) * 16 + (lane & 15);
        const int kb   = kg * 64;

        u64 w[3][32];
#pragma unroll
        for (int i = 0; i < 32; i++)
#pragma unroll
            for (int c = 0; c < 3; c++)
                w[c][i] = pack2(U[(kb + 2*i) * G_ + u + c*128],
                                U[(kb + 2*i + 1) * G_ + u + c*128]);

        for (int i = tid; i < 2 * 2 * 68; i += 256)
            (&h_sm[0][0][0])[i] = 0.0f;
        __syncthreads();

        for (int p = 0; p <= 2 * T_; p++) {
            if ((p >> 1) < T_) {
                const int r = p & 1;
                const float* hs = &h_sm[r][kg][0];
                u64 ax = 0, ay = 0, bx = 0, by = 0, cx = 0, cy = 0;
#pragma unroll
                for (int i2 = 0; i2 < 16; i2++) {
                    ulonglong2 hv = *(const ulonglong2*)&hs[4*i2];
                    ax = fma2(hv.x, w[0][2*i2],     ax);
                    ay = fma2(hv.y, w[0][2*i2 + 1], ay);
                    bx = fma2(hv.x, w[1][2*i2],     bx);
                    by = fma2(hv.y, w[1][2*i2 + 1], by);
                    cx = fma2(hv.x, w[2][2*i2],     cx);
                    cy = fma2(hv.y, w[2][2*i2 + 1], cy);
                }
                float pa, pb, pc, pd, pe, pf;
                unpack2(ax, pa, pb); unpack2(ay, pc, pd);
                float s0 = (pa + pb) + (pc + pd);
                unpack2(bx, pa, pb); unpack2(by, pc, pd);
                float s1 = (pa + pb) + (pc + pd);
                unpack2(cx, pe, pf); unpack2(cy, pc, pd);
                float s2 = (pe + pf) + (pc + pd);
                s0 += __shfl_xor_sync(0xffffffffu, s0, 16);
                s1 += __shfl_xor_sync(0xffffffffu, s1, 16);
                s2 += __shfl_xor_sync(0xffffffffu, s2, 16);
                if (lane < 16) {
                    rec_sm[r][u]       = s0;
                    rec_sm[r][u + 128] = s1;
                    rec_sm[r][u + 256] = s2;
                }
            }
            __syncthreads();
        }
    } else {
        // ---------------- epilogue role (warp 8) ----------------
        const int et = tid & 31;
        const int u4 = et * 4;
        const float* xr0 = xp + (size_t)b0 * T_ * G_;
        const float* xr1 = xp + (size_t)(b0 + 1) * T_ * G_;
        float* o0 = out + (size_t)b0 * T_ * H_;
        float* o1 = out + (size_t)(b0 + 1) * T_ * H_;

        const float4 bz4 = *(const float4*)&brec[u4];
        const float4 br4 = *(const float4*)&brec[u4 + 128];
        const float4 bh4 = *(const float4*)&brec[u4 + 256];

        float hp[2][4] = {{0,0,0,0},{0,0,0,0}};
        float4 cz, cr, ch;     // xp for this phase's epilogue target
        __syncthreads();

        for (int p = 0; p <= 2 * T_; p++) {
            // prefetch xp for phase p+1's epilogue = (row p&1, t p>>1)
            float4 nz, nr, nh;
            if ((p >> 1) < T_) {
                const float* s = ((p & 1) ? xr1 : xr0) + (size_t)(p >> 1) * G_;
                nz = *(const float4*)&s[u4];
                nr = *(const float4*)&s[u4 + 128];
                nh = *(const float4*)&s[u4 + 256];
            }
            if (p > 0) {
                const int er = (p - 1) & 1;
                const int et_t = (p - 1) >> 1;
                float4 rz4 = *(const float4*)&rec_sm[er][u4];
                float4 rr4 = *(const float4*)&rec_sm[er][u4 + 128];
                float4 rh4 = *(const float4*)&rec_sm[er][u4 + 256];
                float4 hn;
                {
                    float z  = sigf(cz.x + rz4.x + bz4.x);
                    float rg = sigf(cr.x + rr4.x + br4.x);
                    float hh = tanh_fast(ch.x + rg * (rh4.x + bh4.x));
                    hn.x = hh + z * (hp[er][0] - hh); hp[er][0] = hn.x;
                    z  = sigf(cz.y + rz4.y + bz4.y);
                    rg = sigf(cr.y + rr4.y + br4.y);
                    hh = tanh_fast(ch.y + rg * (rh4.y + bh4.y));
                    hn.y = hh + z * (hp[er][1] - hh); hp[er][1] = hn.y;
                    z  = sigf(cz.z + rz4.z + bz4.z);
                    rg = sigf(cr.z + rr4.z + br4.z);
                    hh = tanh_fast(ch.z + rg * (rh4.z + bh4.z));
                    hn.z = hh + z * (hp[er][2] - hh); hp[er][2] = hn.z;
                    z  = sigf(cz.w + rz4.w + bz4.w);
                    rg = sigf(cr.w + rr4.w + br4.w);
                    hh = tanh_fast(ch.w + rg * (rh4.w + bh4.w));
                    hn.w = hh + z * (hp[er][3] - hh); hp[er][3] = hn.w;
                }
                *(float4*)&h_sm[er][u4 >> 6][u4 & 63] = hn;
                *(float4*)&(er ? o1 : o0)[(size_t)et_t * H_ + u4] = hn;
            }
            cz = nz; cr = nr; ch = nh;
            __syncthreads();
        }
    }
}

// ---------------------------------------------------------------------------
extern "C" void kernel_launch(void* const* d_in, const int* in_sizes, int n_in,
                              void* d_out, int out_size)
{
    const float* x  = (const float*)d_in[0];
    const float* W0 = (const float*)d_in[1];
    const float* U0 = (const float*)d_in[2];
    const float* b0 = (const float*)d_in[3];
    const float* W1 = (const float*)d_in[4];
    const float* U1 = (const float*)d_in[5];
    const float* b1 = (const float*)d_in[6];
    float* out = (float*)d_out;

    float *xp, *h0;
    cudaGetSymbolAddress((void**)&xp, g_xp);
    cudaGetSymbolAddress((void**)&h0, g_h0);

    const int PROJ_GRID = 1024;
    const int rpb = BT_ / PROJ_GRID;   // 128 rows per block

    // layer 0
    proj_kernel<<<PROJ_GRID, 384>>>(x, W0, b0 /*b_in*/, xp, rpb);
    gru_scan<<<B_ / 2, 288>>>(U0, b0 + G_ /*b_rec*/, xp, h0);
    // layer 1
    proj_kernel<<<PROJ_GRID, 384>>>(h0, W1, b1, xp, rpb);
    gru_scan<<<B_ / 2, 288>>>(U1, b1 + G_, xp, out);
}

// round 10
// speedup vs baseline: 2.8717x; 2.8717x over previous
#include <cuda_runtime.h>
#include <cstdint>

#define B_ 256
#define T_ 512
#define D_ 128
#define H_ 128
#define G_ 384          // 3H, gate order z|r|h
#define BT_ (B_*T_)

__device__ float g_xp[(size_t)BT_ * G_];   // 201 MB scratch
__device__ float g_h0[(size_t)BT_ * H_];   // 67 MB scratch

typedef unsigned long long u64;

static __device__ __forceinline__ u64 pack2(float a, float b) {
    u64 r; asm("mov.b64 %0, {%1, %2};" : "=l"(r) : "f"(a), "f"(b)); return r;
}
static __device__ __forceinline__ void unpack2(u64 v, float &a, float &b) {
    asm("mov.b64 {%0, %1}, %2;" : "=f"(a), "=f"(b) : "l"(v));
}
static __device__ __forceinline__ u64 fma2(u64 a, u64 b, u64 c) {
    u64 d; asm("fma.rn.f32x2 %0, %1, %2, %3;" : "=l"(d) : "l"(a), "l"(b), "l"(c)); return d;
}
// MUFU tanh (sm_75+ PTX, not arch-'a' gated)
static __device__ __forceinline__ float tanh_mufu(float x) {
    float r; asm("tanh.approx.f32 %0, %1;" : "=f"(r) : "f"(x)); return r;
}
static __device__ __forceinline__ float sig_mufu(float x) {
    return fmaf(0.5f, tanh_mufu(0.5f * x), 0.5f);
}

// ---------------------------------------------------------------------------
// Projection (measured 332us/layer in R6 config): 384 threads =
// 4 kg x 96 jg x 4 cols; W in regs; 8 rows/iter; smem partial reduction.
// ---------------------------------------------------------------------------
#define PR_ 8
__global__ __launch_bounds__(384, 1)
void proj_kernel(const float* __restrict__ x, const float* __restrict__ W,
                 const float* __restrict__ bias, float* __restrict__ out,
                 int rows_per_block)
{
    __shared__ __align__(16) float x_sm[2][PR_][D_];
    __shared__ __align__(16) float part[PR_][4][G_];   // 48 KB
    const int tid = threadIdx.x;
    const int kg  = tid / 96;
    const int jg  = tid - kg * 96;
    const int j0  = jg * 4;
    const int kb  = kg * 32;

    u64 w2[16][4];
#pragma unroll
    for (int i = 0; i < 16; i++)
#pragma unroll
        for (int jj = 0; jj < 4; jj++)
            w2[i][jj] = pack2(W[(kb + 2*i) * G_ + j0 + jj],
                              W[(kb + 2*i + 1) * G_ + j0 + jj]);
    const float bj = bias[tid];

    const int row0 = blockIdx.x * rows_per_block;
    if (tid < PR_ * D_ / 4)
        ((float4*)&x_sm[0][0][0])[tid] =
            ((const float4*)(x + (size_t)row0 * D_))[tid];
    __syncthreads();

    const int iters = rows_per_block / PR_;
    int buf = 0;
    for (int it = 0; it < iters; it++) {
        const int rbase = row0 + it * PR_;
        float4 nx;
        const bool pre = (it + 1 < iters) && (tid < PR_ * D_ / 4);
        if (pre)
            nx = ((const float4*)(x + (size_t)(rbase + PR_) * D_))[tid];

#pragma unroll
        for (int r = 0; r < PR_; r++) {
            u64 acc0 = 0, acc1 = 0, acc2 = 0, acc3 = 0;
            const float* xs = &x_sm[buf][r][kb];
#pragma unroll
            for (int i2 = 0; i2 < 8; i2++) {
                ulonglong2 hv = *(const ulonglong2*)&xs[4*i2];
                acc0 = fma2(hv.x, w2[2*i2][0],     acc0);
                acc0 = fma2(hv.y, w2[2*i2 + 1][0], acc0);
                acc1 = fma2(hv.x, w2[2*i2][1],     acc1);
                acc1 = fma2(hv.y, w2[2*i2 + 1][1], acc1);
                acc2 = fma2(hv.x, w2[2*i2][2],     acc2);
                acc2 = fma2(hv.y, w2[2*i2 + 1][2], acc2);
                acc3 = fma2(hv.x, w2[2*i2][3],     acc3);
                acc3 = fma2(hv.y, w2[2*i2 + 1][3], acc3);
            }
            float4 p; float a, b;
            unpack2(acc0, a, b); p.x = a + b;
            unpack2(acc1, a, b); p.y = a + b;
            unpack2(acc2, a, b); p.z = a + b;
            unpack2(acc3, a, b); p.w = a + b;
            *(float4*)&part[r][kg][j0] = p;
        }
        if (pre)
            ((float4*)&x_sm[buf ^ 1][0][0])[tid] = nx;
        __syncthreads();
#pragma unroll
        for (int r = 0; r < PR_; r++) {
            float s = part[r][0][tid] + part[r][1][tid]
                    + part[r][2][tid] + part[r][3][tid] + bj;
            out[(size_t)(rbase + r) * G_ + tid] = s;
        }
        __syncthreads();
        buf ^= 1;
    }
}

// ---------------------------------------------------------------------------
// GRU scan (R6 structure, 427us baseline): 256 threads, 2 rows/CTA.
// Thread (u,kg): kg = lane>>4 (k-half), u = warp*16 + lane&15. Owns gate
// columns {u, u+128, u+256} over its k-half for BOTH rows; single fused
// accumulator chain per (row,col); k-reduce = 3 shfl.xor(16); gate chain via
// MUFU tanh.approx. h double-buffered, ONE barrier per step.
// ---------------------------------------------------------------------------
__global__ __launch_bounds__(256, 1)
void gru_scan(const float* __restrict__ U, const float* __restrict__ brec,
              const float* __restrict__ xp, float* __restrict__ out)
{
    __shared__ __align__(16) float h_sm[2][2][2][68];  // [buf][row][kg][pad]
    const int tid  = threadIdx.x;
    const int lane = tid & 31;
    const int kg   = lane >> 4;
    const int u    = (tid >> 5) * 16 + (lane & 15);
    const int kb   = kg * 64;

    u64 w[3][32];
#pragma unroll
    for (int i = 0; i < 32; i++)
#pragma unroll
        for (int c = 0; c < 3; c++)
            w[c][i] = pack2(U[(kb + 2*i) * G_ + u + c*128],
                            U[(kb + 2*i + 1) * G_ + u + c*128]);
    const float bz = brec[u], br_ = brec[u + 128], bh = brec[u + 256];

    const int row = kg;
    const int b0  = blockIdx.x * 2;
    const float* exr = xp + (size_t)(b0 + row) * T_ * G_;
    float* eo = out + (size_t)(b0 + row) * T_ * H_;

    float xz  = exr[u];
    float xr_ = exr[u + 128];
    float xh  = exr[u + 256];
    float hp  = 0.0f;

    if (tid < 128) {
        h_sm[0][0][tid >> 6][tid & 63] = 0.0f;
        h_sm[0][1][tid >> 6][tid & 63] = 0.0f;
    }
    __syncthreads();

    for (int t = 0; t < T_; t++) {
        const int buf = t & 1;
        float nxz = 0.f, nxr = 0.f, nxh = 0.f;
        if (t + 1 < T_) {
            const float* xn = exr + (size_t)(t + 1) * G_;
            nxz = xn[u]; nxr = xn[u + 128]; nxh = xn[u + 256];
        }

        // --- matvec: both rows x 3 gate columns, fused accumulator chains ---
        u64 a00 = 0, a01 = 0, a02 = 0, a10 = 0, a11 = 0, a12 = 0;
        const float* h0p = &h_sm[buf][0][kg][0];
        const float* h1p = &h_sm[buf][1][kg][0];
#pragma unroll
        for (int i2 = 0; i2 < 16; i2++) {
            ulonglong2 h0 = *(const ulonglong2*)&h0p[4*i2];
            ulonglong2 h1 = *(const ulonglong2*)&h1p[4*i2];
            a00 = fma2(h0.x, w[0][2*i2], a00);
            a00 = fma2(h0.y, w[0][2*i2 + 1], a00);
            a01 = fma2(h0.x, w[1][2*i2], a01);
            a01 = fma2(h0.y, w[1][2*i2 + 1], a01);
            a02 = fma2(h0.x, w[2][2*i2], a02);
            a02 = fma2(h0.y, w[2][2*i2 + 1], a02);
            a10 = fma2(h1.x, w[0][2*i2], a10);
            a10 = fma2(h1.y, w[0][2*i2 + 1], a10);
            a11 = fma2(h1.x, w[1][2*i2], a11);
            a11 = fma2(h1.y, w[1][2*i2 + 1], a11);
            a12 = fma2(h1.x, w[2][2*i2], a12);
            a12 = fma2(h1.y, w[2][2*i2 + 1], a12);
        }
        float s[2][3];
        { float a, b;
          unpack2(a00, a, b); s[0][0] = a + b;
          unpack2(a01, a, b); s[0][1] = a + b;
          unpack2(a02, a, b); s[0][2] = a + b;
          unpack2(a10, a, b); s[1][0] = a + b;
          unpack2(a11, a, b); s[1][1] = a + b;
          unpack2(a12, a, b); s[1][2] = a + b; }

        // k-reduction across kg (lane bit 4)
        float own0 = kg ? s[1][0] : s[0][0];
        float own1 = kg ? s[1][1] : s[0][1];
        float own2 = kg ? s[1][2] : s[0][2];
        float oth0 = kg ? s[0][0] : s[1][0];
        float oth1 = kg ? s[0][1] : s[1][1];
        float oth2 = kg ? s[0][2] : s[1][2];
        float rz = own0 + __shfl_xor_sync(0xffffffffu, oth0, 16) + bz;
        float rr = own1 + __shfl_xor_sync(0xffffffffu, oth1, 16) + br_;
        float rh = own2 + __shfl_xor_sync(0xffffffffu, oth2, 16) + bh;

        // --- gate chain (MUFU tanh) ---
        float z  = sig_mufu(xz + rz);
        float rg = sig_mufu(xr_ + rr);
        float hh = tanh_mufu(xh + rg * rh);
        float hn = hh + z * (hp - hh);
        hp = hn;
        h_sm[buf ^ 1][row][u >> 6][u & 63] = hn;
        eo[(size_t)t * H_ + u] = hn;
        xz = nxz; xr_ = nxr; xh = nxh;
        __syncthreads();
    }
}

// ---------------------------------------------------------------------------
extern "C" void kernel_launch(void* const* d_in, const int* in_sizes, int n_in,
                              void* d_out, int out_size)
{
    const float* x  = (const float*)d_in[0];
    const float* W0 = (const float*)d_in[1];
    const float* U0 = (const float*)d_in[2];
    const float* b0 = (const float*)d_in[3];
    const float* W1 = (const float*)d_in[4];
    const float* U1 = (const float*)d_in[5];
    const float* b1 = (const float*)d_in[6];
    float* out = (float*)d_out;

    float *xp, *h0;
    cudaGetSymbolAddress((void**)&xp, g_xp);
    cudaGetSymbolAddress((void**)&h0, g_h0);

    const int PROJ_GRID = 1024;
    const int rpb = BT_ / PROJ_GRID;   // 128 rows per block

    // layer 0
    proj_kernel<<<PROJ_GRID, 384>>>(x, W0, b0 /*b_in*/, xp, rpb);
    gru_scan<<<B_ / 2, 256>>>(U0, b0 + G_ /*b_rec*/, xp, h0);
    // layer 1
    proj_kernel<<<PROJ_GRID, 384>>>(h0, W1, b1, xp, rpb);
    gru_scan<<<B_ / 2, 256>>>(U1, b1 + G_, xp, out);
}